// round 15
// baseline (speedup 1.0000x reference)
#include <cuda_runtime.h>
#include <math.h>
#include <stdint.h>

// Problem constants (fixed by the benchmark shapes)
#define Bn 256
#define Tn 1024
#define Cn 256          // classes, blank = Cn-1
#define Ln 128
#define EDEAD (-(1 << 28))
#define NCH 4           // ring chunks per element (power of two)
#define CF 8            // frames per chunk
#define CHUNK_F (CF * Cn)          // 2048 floats
#define CHUNK_BYTES (CHUNK_F * 4)  // 8192 bytes
#define RING_F (NCH * CHUNK_F)     // 8192 floats per element
#define FR_F 160                   // staged floats per frame (layout below)
#define STG_F (CF * FR_F)          // staged floats per chunk = 1280

// Staged frame layout (per frame, FR_F floats):
//   [0..31]    pb per lane (warp-uniform value, one copy per lane)
//   [32..95]   (q0,q1) float2 per lane at 32 + 2*lane
//   [96..159]  (q2,q3) float2 per lane at 96 + 2*lane

struct SmemLayout {
    float ring[2][RING_F];                 // 64 KB (TMA-filled)
    float stage[2][2][STG_F];              // 20 KB (gather-produced, 2 bufs)
    unsigned long long mbar[2][NCH];
};

// Named-barrier ids: fill = 1+p*4+buf, free = 3+p*4+buf  (ids 1..8)
#define FILL_ID(p, buf) (1 + (p) * 4 + (buf))
#define FREE_ID(p, buf) (3 + (p) * 4 + (buf))

__device__ __forceinline__ uint32_t s2u(const void* p) {
    return (uint32_t)__cvta_generic_to_shared(p);
}
// exact 2^x; clamps: x <= -127 -> 0.0f, x >= 127 -> 2^127
__device__ __forceinline__ float e2f(int x) {
    x = max(-127, min(127, x));
    return __int_as_float((127 + x) << 23);
}

// ---- packed f32x2 helpers (Blackwell): b64 = adjacent register pair ----
__device__ __forceinline__ unsigned long long pk2(float lo, float hi) {
    unsigned long long r;
    asm("mov.b64 %0, {%1, %2};" : "=l"(r) : "f"(lo), "f"(hi));
    return r;
}
__device__ __forceinline__ float lo2(unsigned long long v) {
    float a, b;
    asm("mov.b64 {%0, %1}, %2;" : "=f"(a), "=f"(b) : "l"(v));
    return a;
}
__device__ __forceinline__ float hi2(unsigned long long v) {
    float a, b;
    asm("mov.b64 {%0, %1}, %2;" : "=f"(a), "=f"(b) : "l"(v));
    return b;
}
__device__ __forceinline__ unsigned long long add2(unsigned long long a,
                                                   unsigned long long b) {
    unsigned long long d;
    asm("add.rn.f32x2 %0, %1, %2;" : "=l"(d) : "l"(a), "l"(b));
    return d;
}
__device__ __forceinline__ unsigned long long mul2(unsigned long long a,
                                                   unsigned long long b) {
    unsigned long long d;
    asm("mul.rn.f32x2 %0, %1, %2;" : "=l"(d) : "l"(a), "l"(b));
    return d;
}
__device__ __forceinline__ unsigned long long fma2(unsigned long long a,
                                                   unsigned long long b,
                                                   unsigned long long c) {
    unsigned long long d;
    asm("fma.rn.f32x2 %0, %1, %2, %3;" : "=l"(d) : "l"(a), "l"(b), "l"(c));
    return d;
}

__device__ __forceinline__ void mbar_init(uint32_t a, uint32_t cnt) {
    asm volatile("mbarrier.init.shared.b64 [%0], %1;" :: "r"(a), "r"(cnt) : "memory");
}
__device__ __forceinline__ void mbar_expect(uint32_t a, uint32_t tx) {
    asm volatile("mbarrier.arrive.expect_tx.shared.b64 _, [%0], %1;"
                 :: "r"(a), "r"(tx) : "memory");
}
__device__ __forceinline__ void bulk_g2s(uint32_t dst, const void* src,
                                         uint32_t bytes, uint32_t mbar) {
    asm volatile("cp.async.bulk.shared::cta.global.mbarrier::complete_tx::bytes "
                 "[%0], [%1], %2, [%3];"
                 :: "r"(dst), "l"(src), "r"(bytes), "r"(mbar) : "memory");
}
__device__ __forceinline__ void mbar_wait(uint32_t a, uint32_t parity) {
    uint32_t done;
    asm volatile("{\n\t.reg .pred p;\n\t"
                 "mbarrier.try_wait.parity.acquire.cta.shared::cta.b64 p, [%1], %2;\n\t"
                 "selp.b32 %0, 1, 0, p;\n\t}"
                 : "=r"(done) : "r"(a), "r"(parity) : "memory");
    if (!done) {
        asm volatile("{\n\t.reg .pred P1;\n\t"
                     "WL%=:\n\t"
                     "mbarrier.try_wait.parity.acquire.cta.shared::cta.b64 P1, [%0], %1;\n\t"
                     "@P1 bra WD%=;\n\t"
                     "bra WL%=;\n\t"
                     "WD%=:\n\t}"
                     :: "r"(a), "r"(parity) : "memory");
    }
}
__device__ __forceinline__ void bar_arrive64(int id) {
    asm volatile("bar.arrive %0, 64;" :: "r"(id) : "memory");
}
__device__ __forceinline__ void bar_wait64(int id) {
    asm volatile("bar.sync %0, 64;" :: "r"(id) : "memory");
}

// Per-element recurrence state, PACKED: lane owns states 8l..8l+7 as
// A0=(m0,m2) A1=(m4,m6) O0=(m1,m3) O1=(m5,m7), shared exponent E.
// Mantissas stay RAW between groups; each group boundary does ONE merged
// normalize+align scale pass. State 256 carried as scalar (lane 31 valid).
struct Ctc {
    unsigned long long A0, A1, O0, O1;
    unsigned long long K0, K1;          // skip flags packed (k1,k3),(k5,k7)
    int   E;
    float m9; int e9;
};

// Run NS (==4, or 3 for the first partial group) forward steps.
// INVARIANTS (load-bearing; learned from R8/R13 NaNs):
//  - NS <= 4: intra-group shrink stays above 2^-93 (no denormal max)
//  - group length 4 == octet_size/2: revival wavefront (2 states/step)
//    crosses octet boundaries only AT group boundaries (no stale-k inf).
template <int NS>
__device__ __forceinline__ void ctc_group(Ctc& S, const float* __restrict__ sfr,
                                          int f0, int lane)
{
    // ---- merged boundary: normalize + align in ONE scale pass ----
    float a0 = lo2(S.A0), a2 = hi2(S.A0), a4 = lo2(S.A1), a6 = hi2(S.A1);
    float b1 = lo2(S.O0), b3 = hi2(S.O0), b5 = lo2(S.O1), b7 = hi2(S.O1);
    float mx = fmaxf(fmaxf(fmaxf(a0, b1), fmaxf(a2, b3)),
                     fmaxf(fmaxf(a4, b5), fmaxf(a6, b7)));
    int ef = (__float_as_int(mx) >> 23) & 0xFF;
    int Et = S.E + ef - 127;                 // true octet exponent
    int pT1 = __shfl_up_sync(0xffffffffu, Et, 1);
    int pT2 = __shfl_up_sync(0xffffffffu, Et, 2);
    if (lane == 0) pT1 = EDEAD;
    if (lane < 2)  pT2 = EDEAD;
    int bse  = max(Et, pT1);
    int pbse = max(pT1, pT2);                // neighbor's base (EDEAD lane 0)
    int k = min(pbse - bse, 254);
    int ka = k / 2, kb = k - ka;             // two exact factors, |k| <= 254
    float dsc1 = e2f(ka), dsc2 = e2f(kb);
    float cs = e2f(S.E - bse);               // combined normalize+align scale
    unsigned long long CS = pk2(cs, cs);
    S.A0 = mul2(CS, S.A0); S.A1 = mul2(CS, S.A1);
    S.O0 = mul2(CS, S.O0); S.O1 = mul2(CS, S.O1);
    S.E = bse;
    // state-256 scalar: merged normalize+align (lane-local)
    int ef9 = (__float_as_int(S.m9) >> 23) & 0xFF;
    int e9t = S.e9 + ef9 - 127;
    int b9 = max(e9t, bse);
    S.m9 *= e2f(S.e9 - b9);
    S.e9 = b9;
    float sp9 = e2f(bse - b9);

    // ---- NS packed steps; probs via 1 LDS.32 + 2 LDS.64 (conflict-free) ----
    #pragma unroll
    for (int f = 0; f < NS; ++f) {
        const float* sf = sfr + (f0 + f) * FR_F;
        float pb = sf[lane];
        unsigned long long Qa = *(const unsigned long long*)(sf + 32 + 2 * lane);
        unsigned long long Qb = *(const unsigned long long*)(sf + 96 + 2 * lane);
        float om7 = hi2(S.O1);
        float pm7 = __shfl_up_sync(0xffffffffu, om7, 1);
        float y7 = (pm7 * dsc1) * dsc2;
        unsigned long long bsh0 = pk2(y7, lo2(S.O0));        // (y7, m1)
        unsigned long long bsh1 = pk2(hi2(S.O0), lo2(S.O1)); // (m3, m5)
        unsigned long long ue0 = add2(S.A0, bsh0);           // (n0, u2)
        unsigned long long ue1 = add2(S.A1, bsh1);           // (u4, u6)
        unsigned long long uo0 = add2(fma2(S.K0, bsh0, S.A0), S.O0); // (n1,u3)
        unsigned long long uo1 = add2(fma2(S.K1, bsh1, S.A1), S.O1); // (u5,u7)
        unsigned long long PBp = pk2(pb, pb);
        S.A0 = mul2(PBp, ue0); S.A1 = mul2(PBp, ue1);
        S.O0 = mul2(Qa, uo0);  S.O1 = mul2(Qb, uo1);
        S.m9 = pb * fmaf(om7, sp9, S.m9);   // state 256: pb*(a256+a255_old)
    }
    // NO epilogue: mantissas stay raw until the next group's boundary pass.
}

__global__ void __launch_bounds__(128, 1)
ctc_px_kernel(const int* __restrict__ labels,
              const float* __restrict__ ypred,
              float* __restrict__ out)
{
    extern __shared__ char smraw[];
    SmemLayout* sm = (SmemLayout*)smraw;
    const int lane = threadIdx.x & 31;
    const int warp = threadIdx.x >> 5;

    if (warp >= 2) {
        // ================= GATHER warp: TMA ring + scattered re-layout =======
        const int p = warp - 2;
        const int b = blockIdx.x * 2 + p;
        const float* __restrict__ row = ypred + (size_t)b * (size_t)(Tn * Cn);
        const int* __restrict__ lab = labels + b * Ln;
        const int c0 = __ldg(lab + 4 * lane + 0);
        const int c1 = __ldg(lab + 4 * lane + 1);
        const int c2 = __ldg(lab + 4 * lane + 2);
        const int c3 = __ldg(lab + 4 * lane + 3);
        float* ring = sm->ring[p];
        const uint32_t mb0 = s2u(&sm->mbar[p][0]);

        if (lane == 0) {
            #pragma unroll
            for (int s = 0; s < NCH; ++s) mbar_init(mb0 + 8 * s, 1);
        }
        asm volatile("fence.proxy.async.shared::cta;" ::: "memory");
        __syncwarp();
        if (lane == 0) {
            #pragma unroll
            for (int s = 0; s < NCH; ++s) {
                mbar_expect(mb0 + 8 * s, CHUNK_BYTES);
                bulk_g2s(s2u(ring + s * CHUNK_F), row + s * CHUNK_F,
                         CHUNK_BYTES, mb0 + 8 * s);
            }
        }

        #pragma unroll 1
        for (int ck = 0; ck < Tn / CF; ++ck) {
            int slot = ck & (NCH - 1);
            int buf  = ck & 1;
            mbar_wait(mb0 + 8 * slot, (ck >> 2) & 1);
            if (ck >= 2) bar_wait64(FREE_ID(p, buf));   // compute freed buf?
            const float* rb = ring + slot * CHUNK_F;
            float* sb = sm->stage[p][buf];
            #pragma unroll
            for (int f = 0; f < CF; ++f) {
                const float* fr = rb + f * Cn;
                float vb = fr[Cn - 1] + 1e-7f;
                float v0 = fr[c0] + 1e-7f;
                float v1 = fr[c1] + 1e-7f;
                float v2 = fr[c2] + 1e-7f;
                float v3 = fr[c3] + 1e-7f;
                float* sfm = sb + f * FR_F;
                sfm[lane] = vb;
                *(float2*)(sfm + 32 + 2 * lane) = make_float2(v0, v1);
                *(float2*)(sfm + 96 + 2 * lane) = make_float2(v2, v3);
            }
            bar_arrive64(FILL_ID(p, buf));              // buf filled
            int nk = ck + NCH;                          // refill ring slot
            if (nk < Tn / CF && lane == 0) {
                mbar_expect(mb0 + 8 * slot, CHUNK_BYTES);
                bulk_g2s(s2u(ring + slot * CHUNK_F), row + (size_t)nk * CHUNK_F,
                         CHUNK_BYTES, mb0 + 8 * slot);
            }
        }
        return;
    }

    // ================= COMPUTE warp: one element, packed datapath ===========
    const int p = warp;
    const int b = blockIdx.x * 2 + p;
    const float* __restrict__ row = ypred + (size_t)b * (size_t)(Tn * Cn);
    const int* __restrict__ lab = labels + b * Ln;

    Ctc S;
    {
        int c0 = __ldg(lab + 4 * lane + 0);
        int c1 = __ldg(lab + 4 * lane + 1);
        int c2 = __ldg(lab + 4 * lane + 2);
        int c3 = __ldg(lab + 4 * lane + 3);
        int cm1 = __shfl_up_sync(0xffffffffu, c3, 1);
        float k1 = (lane > 0 && c0 != cm1) ? 1.0f : 0.0f;
        float k3 = (c1 != c0) ? 1.0f : 0.0f;
        float k5 = (c2 != c1) ? 1.0f : 0.0f;
        float k7 = (c3 != c2) ? 1.0f : 0.0f;
        S.K0 = pk2(k1, k3);
        S.K1 = pk2(k5, k7);
        S.A0 = S.A1 = S.O0 = S.O1 = pk2(0.0f, 0.0f);
        S.E = EDEAD; S.m9 = 0.0f; S.e9 = EDEAD;
        // t=0: states 0 (blank) and 1 (label 0) live on lane 0
        float v0 = __ldg(row + (Cn - 1)) + 1e-7f;
        float v1 = __ldg(row + c0) + 1e-7f;
        float mxv = fmaxf(v0, v1);
        int ef = (__float_as_int(mxv) >> 23) & 0xFF;
        float scr = __int_as_float((254 - ef) << 23);
        if (lane == 0) {
            S.E = ef - 127;
            S.A0 = pk2(v0 * scr, 0.0f);     // m0
            S.O0 = pk2(v1 * scr, 0.0f);     // m1
        }
    }

    #pragma unroll 1
    for (int ck = 0; ck < Tn / CF; ++ck) {
        int buf = ck & 1;
        bar_wait64(FILL_ID(p, buf));                    // staged chunk ready
        const float* sfr = sm->stage[p][buf];
        if (ck == 0) {              // frame 0 consumed by init; 7 steps
            ctc_group<4>(S, sfr, 1, lane);
            ctc_group<3>(S, sfr, 5, lane);
        } else {
            ctc_group<4>(S, sfr, 0, lane);
            ctc_group<4>(S, sfr, 4, lane);
        }
        bar_arrive64(FREE_ID(p, buf));                  // buf consumed
    }

    // loss = -log(alpha[255] + alpha[256]); both live on lane 31.
    // Mantissas are RAW: normalize each before combining.
    if (lane == 31) {
        float m7 = hi2(S.O1);
        int ef7 = (__float_as_int(m7) >> 23) & 0xFF;
        int E7 = S.E + ef7 - 127;
        float m7n = m7 * e2f(127 - ef7);
        int ef9 = (__float_as_int(S.m9) >> 23) & 0xFF;
        int E9 = S.e9 + ef9 - 127;
        float m9n = S.m9 * e2f(127 - ef9);
        int em = max(E7, E9);
        float tot = fmaf(m7n, e2f(E7 - em), m9n * e2f(E9 - em));
        out[b] = -(logf(tot) + (float)em * 0.69314718055994530942f);
    }
}

extern "C" void kernel_launch(void* const* d_in, const int* in_sizes, int n_in,
                              void* d_out, int out_size)
{
    const int*   labels;
    const float* ypred;
    if (in_sizes[0] == Bn * Ln) {
        labels = (const int*)d_in[0];
        ypred  = (const float*)d_in[1];
    } else {
        labels = (const int*)d_in[1];
        ypred  = (const float*)d_in[0];
    }
    const int smem = (int)sizeof(SmemLayout);      // ~84 KB
    cudaFuncSetAttribute(ctc_px_kernel,
                         cudaFuncAttributeMaxDynamicSharedMemorySize, smem);
    ctc_px_kernel<<<Bn / 2, 128, smem>>>(labels, ypred, (float*)d_out);
}

// round 16
// speedup vs baseline: 1.0491x; 1.0491x over previous
#include <cuda_runtime.h>
#include <math.h>
#include <stdint.h>

// Problem constants (fixed by the benchmark shapes)
#define Bn 256
#define Tn 1024
#define Cn 256          // classes, blank = Cn-1
#define Ln 128
#define EDEAD (-(1 << 28))
#define NCH 2           // ring chunks per element (power of two)
#define CF 16           // frames per chunk
#define CHUNK_F (CF * Cn)          // 4096 floats
#define CHUNK_BYTES (CHUNK_F * 4)  // 16384 bytes
#define RING_F (NCH * CHUNK_F)     // 8192 floats per element (32 KB)
#define STG_F (CF * 5 * 32)        // staged floats per chunk = 2560

struct SmemLayout {
    float ring[2][RING_F];                 // 64 KB (TMA-filled)
    float stage[2][2][STG_F];              // 40 KB (gather-produced, 2 bufs)
    unsigned long long mbar[2][NCH];
};

// Named-barrier ids: fill = 1+p*4+buf, free = 3+p*4+buf  (ids 1..8)
#define FILL_ID(p, buf) (1 + (p) * 4 + (buf))
#define FREE_ID(p, buf) (3 + (p) * 4 + (buf))

__device__ __forceinline__ uint32_t s2u(const void* p) {
    return (uint32_t)__cvta_generic_to_shared(p);
}
// exact 2^x; clamps: x <= -127 -> 0.0f, x >= 127 -> 2^127
__device__ __forceinline__ float e2f(int x) {
    x = max(-127, min(127, x));
    return __int_as_float((127 + x) << 23);
}
__device__ __forceinline__ void mbar_init(uint32_t a, uint32_t cnt) {
    asm volatile("mbarrier.init.shared.b64 [%0], %1;" :: "r"(a), "r"(cnt) : "memory");
}
__device__ __forceinline__ void mbar_expect(uint32_t a, uint32_t tx) {
    asm volatile("mbarrier.arrive.expect_tx.shared.b64 _, [%0], %1;"
                 :: "r"(a), "r"(tx) : "memory");
}
__device__ __forceinline__ void bulk_g2s(uint32_t dst, const void* src,
                                         uint32_t bytes, uint32_t mbar) {
    asm volatile("cp.async.bulk.shared::cta.global.mbarrier::complete_tx::bytes "
                 "[%0], [%1], %2, [%3];"
                 :: "r"(dst), "l"(src), "r"(bytes), "r"(mbar) : "memory");
}
__device__ __forceinline__ void mbar_wait(uint32_t a, uint32_t parity) {
    uint32_t done;
    asm volatile("{\n\t.reg .pred p;\n\t"
                 "mbarrier.try_wait.parity.acquire.cta.shared::cta.b64 p, [%1], %2;\n\t"
                 "selp.b32 %0, 1, 0, p;\n\t}"
                 : "=r"(done) : "r"(a), "r"(parity) : "memory");
    if (!done) {
        asm volatile("{\n\t.reg .pred P1;\n\t"
                     "WL%=:\n\t"
                     "mbarrier.try_wait.parity.acquire.cta.shared::cta.b64 P1, [%0], %1;\n\t"
                     "@P1 bra WD%=;\n\t"
                     "bra WL%=;\n\t"
                     "WD%=:\n\t}"
                     :: "r"(a), "r"(parity) : "memory");
    }
}
__device__ __forceinline__ void bar_arrive64(int id) {
    asm volatile("bar.arrive %0, 64;" :: "r"(id) : "memory");
}
__device__ __forceinline__ void bar_wait64(int id) {
    asm volatile("bar.sync %0, 64;" :: "r"(id) : "memory");
}

// Per-element recurrence state: lane owns states 8l..8l+7 as octet block-float.
// Mantissas are kept RAW between groups (value = m * 2^E, m unnormalized);
// each group boundary does ONE combined normalize+align scale pass.
struct Ctc {
    float m0, m1, m2, m3, m4, m5, m6, m7;
    int   E;
    float m9; int e9;
    float k1, k3, k5, k7;
};

// Run NS (==4, or 3 for the first partial group) forward steps reading staged
// probs (conflict-free LDS; eps pre-added by the gather warp).
// INVARIANTS (all load-bearing, learned from R8/R13 NaNs):
//  - NS <= 4: intra-group mantissa shrink stays above 2^-93 (no denormal max)
//  - group length 4 == octet_size/2: the revival wavefront (2 states/step)
//    crosses octet boundaries only AT group boundaries, so a neighbor's m7
//    can never turn nonzero mid-group while our k is stale (=254) -> no inf.
// Boundary = single merged pass: raw max -> true exponent Et -> shfl Et ->
// one combined scale cs = 2^(E_old - bse) (normalize + align in one mul set).
template <int NS>
__device__ __forceinline__ void ctc_group(Ctc& S, const float* __restrict__ sbl,
                                          int f0, int lane)
{
    // ---- merged boundary: normalize + align in ONE scale pass ----
    float mx = fmaxf(fmaxf(fmaxf(S.m0, S.m1), fmaxf(S.m2, S.m3)),
                     fmaxf(fmaxf(S.m4, S.m5), fmaxf(S.m6, S.m7)));
    int ef = (__float_as_int(mx) >> 23) & 0xFF;
    int Et = S.E + ef - 127;                 // true octet exponent
    int pT1 = __shfl_up_sync(0xffffffffu, Et, 1);
    int pT2 = __shfl_up_sync(0xffffffffu, Et, 2);
    if (lane == 0) pT1 = EDEAD;
    if (lane < 2)  pT2 = EDEAD;
    int bse  = max(Et, pT1);
    int pbse = max(pT1, pT2);                // neighbor's base (EDEAD lane 0)
    int k = min(pbse - bse, 254);
    int ka = k / 2, kb = k - ka;             // two exact factors, |k| <= 254
    float dsc1 = e2f(ka), dsc2 = e2f(kb);
    float cs = e2f(S.E - bse);               // = 2^(127-ef) * 2^(Et-bse)
    S.m0 *= cs; S.m1 *= cs; S.m2 *= cs; S.m3 *= cs;
    S.m4 *= cs; S.m5 *= cs; S.m6 *= cs; S.m7 *= cs;
    S.E = bse;
    // state-256 scalar: same merged normalize+align (lane-local)
    int ef9 = (__float_as_int(S.m9) >> 23) & 0xFF;
    int e9t = S.e9 + ef9 - 127;
    int b9 = max(e9t, bse);
    S.m9 *= e2f(S.e9 - b9);
    S.e9 = b9;
    float sp9 = e2f(bse - b9);

    // ---- NS cheap steps; probs via conflict-free staged LDS ----
    #pragma unroll
    for (int f = 0; f < NS; ++f) {
        const float* sf = sbl + (f0 + f) * (5 * 32);
        float pb = sf[0];
        float q0 = sf[32], q1 = sf[64], q2 = sf[96], q3 = sf[128];
        float om7 = S.m7;
        float pm7 = __shfl_up_sync(0xffffffffu, S.m7, 1);
        float y7 = (pm7 * dsc1) * dsc2;
        float n0 = S.m0 + y7;
        float n1 = fmaf(S.k1, y7, S.m0) + S.m1;
        float u2 = S.m2 + S.m1;
        float u3 = fmaf(S.k3, S.m1, S.m2) + S.m3;
        float u4 = S.m4 + S.m3;
        float u5 = fmaf(S.k5, S.m3, S.m4) + S.m5;
        float u6 = S.m6 + S.m5;
        float u7 = fmaf(S.k7, S.m5, S.m6) + S.m7;
        S.m0 = pb * n0; S.m1 = q0 * n1;
        S.m2 = pb * u2; S.m3 = q1 * u3;
        S.m4 = pb * u4; S.m5 = q2 * u5;
        S.m6 = pb * u6; S.m7 = q3 * u7;
        S.m9 = pb * fmaf(om7, sp9, S.m9);   // state 256: pb*(a256+a255_old)
    }
    // NO epilogue: mantissas stay raw until the next group's boundary pass.
}

__global__ void __launch_bounds__(128, 1)
ctc_c16_kernel(const int* __restrict__ labels,
               const float* __restrict__ ypred,
               float* __restrict__ out)
{
    extern __shared__ char smraw[];
    SmemLayout* sm = (SmemLayout*)smraw;
    const int lane = threadIdx.x & 31;
    const int warp = threadIdx.x >> 5;

    if (warp >= 2) {
        // ================= GATHER warp: TMA ring + scattered re-layout =======
        const int p = warp - 2;
        const int b = blockIdx.x * 2 + p;
        const float* __restrict__ row = ypred + (size_t)b * (size_t)(Tn * Cn);
        const int* __restrict__ lab = labels + b * Ln;
        const int c0 = __ldg(lab + 4 * lane + 0);
        const int c1 = __ldg(lab + 4 * lane + 1);
        const int c2 = __ldg(lab + 4 * lane + 2);
        const int c3 = __ldg(lab + 4 * lane + 3);
        float* ring = sm->ring[p];
        const uint32_t mb0 = s2u(&sm->mbar[p][0]);

        if (lane == 0) {
            #pragma unroll
            for (int s = 0; s < NCH; ++s) mbar_init(mb0 + 8 * s, 1);
        }
        asm volatile("fence.proxy.async.shared::cta;" ::: "memory");
        __syncwarp();
        if (lane == 0) {
            #pragma unroll
            for (int s = 0; s < NCH; ++s) {
                mbar_expect(mb0 + 8 * s, CHUNK_BYTES);
                bulk_g2s(s2u(ring + s * CHUNK_F), row + s * CHUNK_F,
                         CHUNK_BYTES, mb0 + 8 * s);
            }
        }

        #pragma unroll 1
        for (int ck = 0; ck < Tn / CF; ++ck) {
            int slot = ck & (NCH - 1);
            int buf  = ck & 1;
            mbar_wait(mb0 + 8 * slot, (ck >> 1) & 1);
            if (ck >= 2) bar_wait64(FREE_ID(p, buf));   // compute freed buf?
            const float* rb = ring + slot * CHUNK_F;
            float* sb = sm->stage[p][buf] + lane;
            #pragma unroll
            for (int f = 0; f < CF; ++f) {
                const float* fr = rb + f * Cn;
                float vb = fr[Cn - 1] + 1e-7f;
                float v0 = fr[c0] + 1e-7f;
                float v1 = fr[c1] + 1e-7f;
                float v2 = fr[c2] + 1e-7f;
                float v3 = fr[c3] + 1e-7f;
                sb[f * 160 + 0]   = vb;
                sb[f * 160 + 32]  = v0;
                sb[f * 160 + 64]  = v1;
                sb[f * 160 + 96]  = v2;
                sb[f * 160 + 128] = v3;
            }
            bar_arrive64(FILL_ID(p, buf));              // buf filled
            int nk = ck + NCH;                          // refill ring slot
            if (nk < Tn / CF && lane == 0) {
                mbar_expect(mb0 + 8 * slot, CHUNK_BYTES);
                bulk_g2s(s2u(ring + slot * CHUNK_F), row + (size_t)nk * CHUNK_F,
                         CHUNK_BYTES, mb0 + 8 * slot);
            }
        }
        return;
    }

    // ================= COMPUTE warp: one element, staged probs ==============
    const int p = warp;
    const int b = blockIdx.x * 2 + p;
    const float* __restrict__ row = ypred + (size_t)b * (size_t)(Tn * Cn);
    const int* __restrict__ lab = labels + b * Ln;

    Ctc S;
    {
        int c0 = __ldg(lab + 4 * lane + 0);
        int c1 = __ldg(lab + 4 * lane + 1);
        int c2 = __ldg(lab + 4 * lane + 2);
        int c3 = __ldg(lab + 4 * lane + 3);
        int cm1 = __shfl_up_sync(0xffffffffu, c3, 1);
        S.k1 = (lane > 0 && c0 != cm1) ? 1.0f : 0.0f;
        S.k3 = (c1 != c0) ? 1.0f : 0.0f;
        S.k5 = (c2 != c1) ? 1.0f : 0.0f;
        S.k7 = (c3 != c2) ? 1.0f : 0.0f;
        S.m0 = S.m1 = S.m2 = S.m3 = S.m4 = S.m5 = S.m6 = S.m7 = 0.0f;
        S.E = EDEAD; S.m9 = 0.0f; S.e9 = EDEAD;
        // t=0: states 0 (blank) and 1 (label 0) live on lane 0
        float v0 = __ldg(row + (Cn - 1)) + 1e-7f;
        float v1 = __ldg(row + c0) + 1e-7f;
        float mx = fmaxf(v0, v1);
        int ef = (__float_as_int(mx) >> 23) & 0xFF;
        float scr = __int_as_float((254 - ef) << 23);
        if (lane == 0) { S.E = ef - 127; S.m0 = v0 * scr; S.m1 = v1 * scr; }
    }

    #pragma unroll 1
    for (int ck = 0; ck < Tn / CF; ++ck) {
        int buf = ck & 1;
        bar_wait64(FILL_ID(p, buf));                    // staged chunk ready
        const float* sbl = sm->stage[p][buf] + lane;
        if (ck == 0) {              // frame 0 consumed by init; 15 steps
            ctc_group<4>(S, sbl, 1, lane);
            ctc_group<4>(S, sbl, 5, lane);
            ctc_group<4>(S, sbl, 9, lane);
            ctc_group<3>(S, sbl, 13, lane);
        } else {                    // four 4-step groups per 16-frame chunk
            ctc_group<4>(S, sbl, 0, lane);
            ctc_group<4>(S, sbl, 4, lane);
            ctc_group<4>(S, sbl, 8, lane);
            ctc_group<4>(S, sbl, 12, lane);
        }
        bar_arrive64(FREE_ID(p, buf));                  // buf consumed
    }

    // loss = -log(alpha[255] + alpha[256]); both live on lane 31.
    // Mantissas are RAW here: normalize each before combining.
    if (lane == 31) {
        int ef7 = (__float_as_int(S.m7) >> 23) & 0xFF;
        int E7 = S.E + ef7 - 127;
        float m7n = S.m7 * e2f(127 - ef7);
        int ef9 = (__float_as_int(S.m9) >> 23) & 0xFF;
        int E9 = S.e9 + ef9 - 127;
        float m9n = S.m9 * e2f(127 - ef9);
        int em = max(E7, E9);
        float tot = fmaf(m7n, e2f(E7 - em), m9n * e2f(E9 - em));
        out[b] = -(logf(tot) + (float)em * 0.69314718055994530942f);
    }
}

extern "C" void kernel_launch(void* const* d_in, const int* in_sizes, int n_in,
                              void* d_out, int out_size)
{
    const int*   labels;
    const float* ypred;
    if (in_sizes[0] == Bn * Ln) {
        labels = (const int*)d_in[0];
        ypred  = (const float*)d_in[1];
    } else {
        labels = (const int*)d_in[1];
        ypred  = (const float*)d_in[0];
    }
    const int smem = (int)sizeof(SmemLayout);      // ~104 KB
    cudaFuncSetAttribute(ctc_c16_kernel,
                         cudaFuncAttributeMaxDynamicSharedMemorySize, smem);
    ctc_c16_kernel<<<Bn / 2, 128, smem>>>(labels, ypred, (float*)d_out);
}